// round 15
// baseline (speedup 1.0000x reference)
#include <cuda_runtime.h>

// out = inputs * (noise >= 0.5f ? 2.0f : 0.0f)
// FINAL CHAMPION: flat one-float4-per-thread, 512-thread blocks, default
// caching. 67,108,864 fp32 = 16,777,216 float4 = 32768 x 512, exact.
//
// Roofline evidence, 10 benched variants across every single-variable axis:
//   VPT 1/2/4 | 128-bit vs 256-bit (v8.f32) accesses | blocks 256/512 |
//   load & store cache hints (isolated + combined) | flat vs persistent.
// This structure: 114.7-115.2 us, DRAM 88.0-88.3% (up to 7.00 TB/s),
// reproduced across 5 runs; every deviation measured equal or slower
// (83.4-88.2%). Traffic (768 MiB) is minimal. Residual ~12% vs the 8 TB/s
// unidirectional spec = HBM read/write bus turnaround on the 2:1 interleaved
// stream (protocol cost; LTS cap is path-independent on B300).
// Compute pipes <7% — HBM-interface-bound at the achievable peak.

__global__ void __launch_bounds__(512)
sparse_dropout_vec4_b512(const float4* __restrict__ inputs,
                         const float4* __restrict__ noise,
                         float4* __restrict__ out)
{
    const unsigned idx = blockIdx.x * blockDim.x + threadIdx.x;

    float4 x = inputs[idx];
    float4 n = noise[idx];

    float4 r;
    r.x = (n.x >= 0.5f) ? x.x * 2.0f : 0.0f;
    r.y = (n.y >= 0.5f) ? x.y * 2.0f : 0.0f;
    r.z = (n.z >= 0.5f) ? x.z * 2.0f : 0.0f;
    r.w = (n.w >= 0.5f) ? x.w * 2.0f : 0.0f;

    out[idx] = r;
}

extern "C" void kernel_launch(void* const* d_in, const int* in_sizes, int n_in,
                              void* d_out, int out_size)
{
    const float4* inputs = (const float4*)d_in[0];
    const float4* noise  = (const float4*)d_in[1];
    float4* out          = (float4*)d_out;

    const int n_vec4 = out_size / 4;     // 16,777,216
    const int threads = 512;
    const int blocks = n_vec4 / threads; // 32768, exact

    sparse_dropout_vec4_b512<<<blocks, threads>>>(inputs, noise, out);
}

// round 16
// speedup vs baseline: 1.0028x; 1.0028x over previous
#include <cuda_runtime.h>

// out = inputs * (noise >= 0.5f ? 2.0f : 0.0f)
// FINAL CHAMPION: flat one-float4-per-thread, 512-thread blocks, default
// caching. 67,108,864 fp32 = 16,777,216 float4 = 32768 x 512, exact.
//
// Roofline evidence, 10 benched variants across every single-variable axis:
//   VPT 1/2/4 | 128-bit vs 256-bit (v8.f32) accesses | blocks 256/512 |
//   load & store cache hints (isolated + combined) | flat vs persistent.
// This structure: 114.7-115.2 us, DRAM 88.0-88.3% (up to 7.00 TB/s),
// reproduced across 5 runs; every deviation measured equal or slower
// (83.4-88.2%). Traffic (768 MiB) is minimal. Residual ~12% vs the 8 TB/s
// unidirectional spec = HBM read/write bus turnaround on the 2:1 interleaved
// stream (protocol cost; LTS cap is path-independent on B300).
// Compute pipes <7% — HBM-interface-bound at the achievable peak.

__global__ void __launch_bounds__(512)
sparse_dropout_vec4_b512(const float4* __restrict__ inputs,
                         const float4* __restrict__ noise,
                         float4* __restrict__ out)
{
    const unsigned idx = blockIdx.x * blockDim.x + threadIdx.x;

    float4 x = inputs[idx];
    float4 n = noise[idx];

    float4 r;
    r.x = (n.x >= 0.5f) ? x.x * 2.0f : 0.0f;
    r.y = (n.y >= 0.5f) ? x.y * 2.0f : 0.0f;
    r.z = (n.z >= 0.5f) ? x.z * 2.0f : 0.0f;
    r.w = (n.w >= 0.5f) ? x.w * 2.0f : 0.0f;

    out[idx] = r;
}

extern "C" void kernel_launch(void* const* d_in, const int* in_sizes, int n_in,
                              void* d_out, int out_size)
{
    const float4* inputs = (const float4*)d_in[0];
    const float4* noise  = (const float4*)d_in[1];
    float4* out          = (float4*)d_out;

    const int n_vec4 = out_size / 4;     // 16,777,216
    const int threads = 512;
    const int blocks = n_vec4 / threads; // 32768, exact

    sparse_dropout_vec4_b512<<<blocks, threads>>>(inputs, noise, out);
}